// round 6
// baseline (speedup 1.0000x reference)
#include <cuda_runtime.h>
#include <cstdint>

// Problem shape (fixed by setup_inputs)
constexpr int Bsz = 8, Np = 8192, Sp = 2048;
constexpr int C1 = 128, C2 = 256, CIN = 384, H1 = 256, H2 = 128;
constexpr int M = Bsz * Np; // 65536 points
constexpr int SLOTS = 512;  // GEMM row-block count (M/128)

// ---------------- scratch (__device__ globals) -------------------------------
__device__ __align__(16) float g_x  [(size_t)M * CIN];  // tf32-rounded concat
__device__ __align__(16) float g_y1 [(size_t)M * H1];   // raw fp32 y1
__device__             int   g_idx [M * 3];
__device__             float g_wt  [M * 3];
__device__ __align__(16) float g_w1r[H1 * CIN];         // tf32-rounded W1
__device__ __align__(16) float g_w2r[H2 * H1];          // tf32-rounded W2
__device__ __align__(16) float g_psum[SLOTS * 256];
__device__ __align__(16) float g_psq [SLOTS * 256];
__device__ __align__(16) float g_scale1[H1], g_shift1[H1];
__device__ __align__(16) float g_scale2[H2], g_shift2[H2];

// ---------------- PTX helpers (sm_80+ only) ----------------------------------
__device__ __forceinline__ uint32_t smem_u32(const void* p) {
    uint32_t a;
    asm("{ .reg .u64 t; cvta.to.shared.u64 t, %1; cvt.u32.u64 %0, t; }"
        : "=r"(a) : "l"(p));
    return a;
}
__device__ __forceinline__ float f2tf32(float f) {   // round-to-nearest tf32
    uint32_t o;
    asm("cvt.rna.tf32.f32 %0, %1;" : "=r"(o) : "f"(f));
    return __uint_as_float(o);
}
#define CP_ASYNC16(dst, src) \
    asm volatile("cp.async.cg.shared.global [%0], [%1], 16;" \
                 :: "r"(dst), "l"(src) : "memory")
#define CP_COMMIT() asm volatile("cp.async.commit_group;" ::: "memory")
#define CP_WAIT1()  asm volatile("cp.async.wait_group 1;" ::: "memory")
__device__ __forceinline__ uint32_t LDS(uint32_t a) {
    uint32_t v;
    asm volatile("ld.shared.b32 %0, [%1];" : "=r"(v) : "r"(a));
    return v;
}
#define MMA_TF32(d, a, b) \
    asm volatile("mma.sync.aligned.m16n8k8.row.col.f32.tf32.tf32.f32 " \
        "{%0,%1,%2,%3}, {%4,%5,%6,%7}, {%8,%9}, {%0,%1,%2,%3};" \
        : "+f"((d)[0]), "+f"((d)[1]), "+f"((d)[2]), "+f"((d)[3]) \
        : "r"((a)[0]), "r"((a)[1]), "r"((a)[2]), "r"((a)[3]), \
          "r"((b)[0]), "r"((b)[1]))

// ---------------- 3-NN per query point ---------------------------------------
__global__ void knn_kernel(const float* __restrict__ xyz1,
                           const float* __restrict__ xyz2) {
    __shared__ float4 sp[Sp];
    const int b = blockIdx.x >> 5;
    const int n = ((blockIdx.x & 31) << 8) + threadIdx.x;
    const float* x2 = xyz2 + (size_t)b * Sp * 3;
    for (int s = threadIdx.x; s < Sp; s += 256) {
        float px = x2[3 * s], py = x2[3 * s + 1], pz = x2[3 * s + 2];
        sp[s] = make_float4(px, py, pz, px * px + py * py + pz * pz);
    }
    __syncthreads();
    const float* q = xyz1 + ((size_t)b * Np + n) * 3;
    const float qx = q[0], qy = q[1], qz = q[2];
    const float q2 = qx * qx + qy * qy + qz * qz;
    float e0 = 3.4e38f, e1 = 3.4e38f, e2v = 3.4e38f;
    int i0 = 0, i1 = 0, i2 = 0;
#pragma unroll 4
    for (int s = 0; s < Sp; s++) {
        float4 p = sp[s];
        float dot = fmaf(qx, p.x, fmaf(qy, p.y, qz * p.z));
        float d2 = (q2 + p.w) - 2.0f * dot;      // same formula as reference
        if (d2 < e2v) {
            if (d2 < e1) {
                e2v = e1; i2 = i1;
                if (d2 < e0) { e1 = e0; i1 = i0; e0 = d2; i0 = s; }
                else         { e1 = d2; i1 = s; }
            } else { e2v = d2; i2 = s; }
        }
    }
    float d0 = sqrtf(fmaxf(e0,  0.f)) + 1e-10f;
    float d1 = sqrtf(fmaxf(e1,  0.f)) + 1e-10f;
    float d2 = sqrtf(fmaxf(e2v, 0.f)) + 1e-10f;
    float w0 = 1.f / d0, w1 = 1.f / d1, w2 = 1.f / d2;
    float inv = 1.f / (w0 + w1 + w2);
    const int m = b * Np + n;
    g_idx[3 * m] = i0; g_idx[3 * m + 1] = i1; g_idx[3 * m + 2] = i2;
    g_wt [3 * m] = w0 * inv; g_wt[3 * m + 1] = w1 * inv; g_wt[3 * m + 2] = w2 * inv;
}

// ---------------- interpolate + concat => x [M x 384] (tf32-rounded) ---------
__global__ void build_x_kernel(const float* __restrict__ f1,
                               const float* __restrict__ f2) {
    const int m = blockIdx.x;
    const int b = m >> 13;
    const int t = threadIdx.x;
    const int i0 = g_idx[3 * m], i1 = g_idx[3 * m + 1], i2 = g_idx[3 * m + 2];
    const float w0 = g_wt[3 * m], w1 = g_wt[3 * m + 1], w2 = g_wt[3 * m + 2];
    const float* r0 = f2 + ((size_t)b * Sp + i0) * C2;
    const float* r1 = f2 + ((size_t)b * Sp + i1) * C2;
    const float* r2 = f2 + ((size_t)b * Sp + i2) * C2;
    float* xr = g_x + (size_t)m * CIN;
    xr[t]       = f2tf32(w0 * r0[t]       + w1 * r1[t]       + w2 * r2[t]);
    xr[t + 128] = f2tf32(w0 * r0[t + 128] + w1 * r1[t + 128] + w2 * r2[t + 128]);
    xr[C2 + t]  = f2tf32(f1[(size_t)m * C1 + t]);
}

// ---------------- weight rounding to tf32 ------------------------------------
__global__ void round_w_kernel(const float* __restrict__ W1,
                               const float* __restrict__ W2) {
    int i = blockIdx.x * 256 + threadIdx.x;
    if (i < H1 * CIN) g_w1r[i] = f2tf32(W1[i]);
    if (i < H2 * H1)  g_w2r[i] = f2tf32(W2[i]);
}

// ---------------- tf32 mma.sync GEMM + fused stats (+ fused BN on A) ---------
// C[M x N] = A'[M x KTOT] * Bw^T;  A' = XFORM ? tf32(relu(A*scale+shift)) : A.
// 128x128 CTA tile, BK=16, 8 warps (4x2), warp tile 32x64.
// Epilogue: per-CTA column sum / sumsq of C written to g_psum/g_psq[slot].
template <int KTOT, bool XFORM>
__global__ void __launch_bounds__(256, 3)
mma_gemm_kernel(const float* __restrict__ A, const float* __restrict__ Bw,
                float* __restrict__ C, int N,
                const float* __restrict__ scale, const float* __restrict__ shift) {
    constexpr int NITER = KTOT / 16;
    constexpr int LDP = 20;                      // padded row stride (floats)
    constexpr int STG_FLOATS = 2 * 128 * LDP;
    extern __shared__ float sm[];
    __shared__ float s_sc[XFORM ? KTOT : 1], s_sh[XFORM ? KTOT : 1];
    __shared__ float s_sum[128], s_sq[128];
    const int tid = threadIdx.x;
    const int lane = tid & 31;
    const int g = lane >> 2, t = lane & 3;
    const int wid = tid >> 5;
    const int wm = wid & 3, wn = wid >> 2;
    const int m0 = blockIdx.x << 7;
    const int n0 = blockIdx.y << 7;
    const uint32_t sbase = smem_u32(sm);

    if (XFORM && tid < KTOT) { s_sc[tid] = scale[tid]; s_sh[tid] = shift[tid]; }
    if (tid < 128) { s_sum[tid] = 0.f; s_sq[tid] = 0.f; }

    const float* Ag = A  + (size_t)m0 * KTOT;
    const float* Bg = Bw + (size_t)n0 * KTOT;

    auto issue = [&](int s, int kc) {
        uint32_t st = sbase + (uint32_t)s * STG_FLOATS * 4;
#pragma unroll
        for (int h = 0; h < 2; h++) {
            int c = h * 256 + tid;
            int row = c >> 2, ko = (c & 3) * 4;
            CP_ASYNC16(st + (row * LDP + ko) * 4,
                       Ag + (size_t)row * KTOT + kc * 16 + ko);
        }
        uint32_t stb = st + 128 * LDP * 4;
#pragma unroll
        for (int h = 0; h < 2; h++) {
            int c = h * 256 + tid;
            int row = c >> 2, ko = (c & 3) * 4;
            CP_ASYNC16(stb + (row * LDP + ko) * 4,
                       Bg + (size_t)row * KTOT + kc * 16 + ko);
        }
    };

    issue(0, 0); CP_COMMIT();
    issue(1, 1); CP_COMMIT();

    float acc[2][8][4];
#pragma unroll
    for (int mt = 0; mt < 2; mt++)
#pragma unroll
        for (int nt = 0; nt < 8; nt++)
#pragma unroll
            for (int j = 0; j < 4; j++) acc[mt][nt][j] = 0.f;

    for (int it = 0; it < NITER; ++it) {
        CP_WAIT1();
        __syncthreads();
        const int nk = it + 2;
        if (nk < NITER) issue(nk % 3, nk);
        CP_COMMIT();
        const uint32_t st = sbase + (uint32_t)(it % 3) * STG_FLOATS * 4;
        const uint32_t aB = st, bB = st + 128 * LDP * 4;
#pragma unroll
        for (int ks = 0; ks < 2; ks++) {
            const int kk = ks * 8;
            uint32_t a[2][4];
#pragma unroll
            for (int mt = 0; mt < 2; mt++) {
                uint32_t p = aB + (((wm * 32 + mt * 16 + g) * LDP) + kk + t) * 4;
                a[mt][0] = LDS(p);
                a[mt][1] = LDS(p + 8 * LDP * 4);
                a[mt][2] = LDS(p + 16);
                a[mt][3] = LDS(p + 8 * LDP * 4 + 16);
            }
            if (XFORM) {
                const int kb = it * 16 + kk;
                float sc0 = s_sc[kb + t],     sh0 = s_sh[kb + t];
                float sc4 = s_sc[kb + t + 4], sh4 = s_sh[kb + t + 4];
#pragma unroll
                for (int mt = 0; mt < 2; mt++) {
                    a[mt][0] = __float_as_uint(f2tf32(fmaxf(fmaf(__uint_as_float(a[mt][0]), sc0, sh0), 0.f)));
                    a[mt][1] = __float_as_uint(f2tf32(fmaxf(fmaf(__uint_as_float(a[mt][1]), sc0, sh0), 0.f)));
                    a[mt][2] = __float_as_uint(f2tf32(fmaxf(fmaf(__uint_as_float(a[mt][2]), sc4, sh4), 0.f)));
                    a[mt][3] = __float_as_uint(f2tf32(fmaxf(fmaf(__uint_as_float(a[mt][3]), sc4, sh4), 0.f)));
                }
            }
#pragma unroll
            for (int nt = 0; nt < 8; nt++) {
                uint32_t b[2];
                uint32_t p = bB + (((wn * 64 + nt * 8 + g) * LDP) + kk + t) * 4;
                b[0] = LDS(p);
                b[1] = LDS(p + 16);
                MMA_TF32(acc[0][nt], a[0], b);
                MMA_TF32(acc[1][nt], a[1], b);
            }
        }
    }
    // ---- write C ------------------------------------------------------------
#pragma unroll
    for (int mt = 0; mt < 2; mt++) {
        int r0 = m0 + wm * 32 + mt * 16 + g;
#pragma unroll
        for (int nt = 0; nt < 8; nt++) {
            int c0 = n0 + wn * 64 + nt * 8 + t * 2;
            *(float2*)&C[(size_t)r0 * N + c0] =
                make_float2(acc[mt][nt][0], acc[mt][nt][1]);
            *(float2*)&C[(size_t)(r0 + 8) * N + c0] =
                make_float2(acc[mt][nt][2], acc[mt][nt][3]);
        }
    }
    // ---- fused per-CTA column stats ----------------------------------------
#pragma unroll
    for (int nt = 0; nt < 8; nt++) {
#pragma unroll
        for (int j = 0; j < 2; j++) {
            float s = 0.f, q = 0.f;
#pragma unroll
            for (int mt = 0; mt < 2; mt++) {
                float v0 = acc[mt][nt][j], v1 = acc[mt][nt][j + 2];
                s += v0 + v1;
                q = fmaf(v0, v0, q); q = fmaf(v1, v1, q);
            }
            s += __shfl_xor_sync(~0u, s, 4);  q += __shfl_xor_sync(~0u, q, 4);
            s += __shfl_xor_sync(~0u, s, 8);  q += __shfl_xor_sync(~0u, q, 8);
            s += __shfl_xor_sync(~0u, s, 16); q += __shfl_xor_sync(~0u, q, 16);
            if (lane < 4) {
                int c = wn * 64 + nt * 8 + t * 2 + j;
                atomicAdd(&s_sum[c], s);
                atomicAdd(&s_sq [c], q);
            }
        }
    }
    __syncthreads();
    if (tid < 128) {
        int col = n0 + tid;
        int ntot = (int)gridDim.y << 7;
        g_psum[(size_t)blockIdx.x * ntot + col] = s_sum[tid];
        g_psq [(size_t)blockIdx.x * ntot + col] = s_sq [tid];
    }
}

// ---------------- final stats reduce (512 slots) -> scale/shift --------------
template <int C>
__global__ void stats_final_kernel(const float* __restrict__ g,
                                   const float* __restrict__ be,
                                   float* __restrict__ scale,
                                   float* __restrict__ shift) {
    __shared__ float ss[8][32], sq[8][32];
    const int x = threadIdx.x, y = threadIdx.y;
    const int c = blockIdx.x * 32 + x;
    float s = 0.f, q = 0.f;
    for (int r = y; r < SLOTS; r += 8) {
        s += g_psum[(size_t)r * C + c];
        q += g_psq [(size_t)r * C + c];
    }
    ss[y][x] = s; sq[y][x] = q;
    __syncthreads();
    if (y == 0) {
#pragma unroll
        for (int yy = 1; yy < 8; yy++) { s += ss[yy][x]; q += sq[yy][x]; }
        const float invM = 1.0f / (float)M;
        float mean = s * invM;
        float var  = fmaf(q, invM, -mean * mean);
        float sc   = g[c] * rsqrtf(var + 1e-5f);
        scale[c] = sc;
        shift[c] = fmaf(-mean, sc, be[c]);   // conv bias cancels in training BN
    }
}

// ---------------- final BN+ReLU in place on d_out ----------------------------
__global__ void bnrelu_out_kernel(float* __restrict__ out) {
    int i = blockIdx.x * blockDim.x + threadIdx.x;
    float4 v = ((float4*)out)[i];
    int c = (i << 2) & (H2 - 1);
    v.x = fmaxf(fmaf(v.x, g_scale2[c],     g_shift2[c]),     0.f);
    v.y = fmaxf(fmaf(v.y, g_scale2[c + 1], g_shift2[c + 1]), 0.f);
    v.z = fmaxf(fmaf(v.z, g_scale2[c + 2], g_shift2[c + 2]), 0.f);
    v.w = fmaxf(fmaf(v.w, g_scale2[c + 3], g_shift2[c + 3]), 0.f);
    ((float4*)out)[i] = v;
}

// ---------------- launch ------------------------------------------------------
extern "C" void kernel_launch(void* const* d_in, const int* in_sizes, int n_in,
                              void* d_out, int out_size) {
    const float* xyz1 = (const float*)d_in[0];
    const float* xyz2 = (const float*)d_in[1];
    const float* f1   = (const float*)d_in[2];
    const float* f2   = (const float*)d_in[3];
    const float* W1   = (const float*)d_in[4];
    const float* g1   = (const float*)d_in[6];
    const float* be1  = (const float*)d_in[7];
    const float* W2   = (const float*)d_in[8];
    const float* g2   = (const float*)d_in[10];
    const float* be2  = (const float*)d_in[11];
    float* out = (float*)d_out;

    float *px, *py1, *pw1, *pw2, *ps1, *pt1, *ps2, *pt2;
    cudaGetSymbolAddress((void**)&px,  g_x);
    cudaGetSymbolAddress((void**)&py1, g_y1);
    cudaGetSymbolAddress((void**)&pw1, g_w1r);
    cudaGetSymbolAddress((void**)&pw2, g_w2r);
    cudaGetSymbolAddress((void**)&ps1, g_scale1);
    cudaGetSymbolAddress((void**)&pt1, g_shift1);
    cudaGetSymbolAddress((void**)&ps2, g_scale2);
    cudaGetSymbolAddress((void**)&pt2, g_shift2);

    constexpr int SMEM = 3 * 2 * 128 * 20 * 4;   // 61440 bytes
    cudaFuncSetAttribute(mma_gemm_kernel<CIN, false>,
                         cudaFuncAttributeMaxDynamicSharedMemorySize, SMEM);
    cudaFuncSetAttribute(mma_gemm_kernel<H1, true>,
                         cudaFuncAttributeMaxDynamicSharedMemorySize, SMEM);

    round_w_kernel<<<(H1 * CIN + 255) / 256, 256>>>(W1, W2);
    knn_kernel<<<Bsz * 32, 256>>>(xyz1, xyz2);
    build_x_kernel<<<M, 128>>>(f1, f2);

    // layer 1: y1 = x @ W1^T (raw fp32 out) + fused col-stats
    mma_gemm_kernel<CIN, false><<<dim3(M / 128, H1 / 128), 256, SMEM>>>(
        px, pw1, py1, H1, nullptr, nullptr);
    stats_final_kernel<H1><<<H1 / 32, dim3(32, 8)>>>(g1, be1, ps1, pt1);

    // layer 2: y2 = tf32(relu(BN1(y1))) @ W2^T + fused col-stats
    mma_gemm_kernel<H1, true><<<dim3(M / 128, H2 / 128), 256, SMEM>>>(
        py1, pw2, out, H2, ps1, pt1);
    stats_final_kernel<H2><<<H2 / 32, dim3(32, 8)>>>(g2, be2, ps2, pt2);

    bnrelu_out_kernel<<<(M * H2 / 4) / 256, 256>>>(out);
}